// round 1
// baseline (speedup 1.0000x reference)
#include <cuda_runtime.h>
#include <math.h>

// ============================================================================
// GroupLorentzConv2d  —  B=16, H=W=64, C=65, OSTAB=4, KS=3
//
// Reduction of the reference:
//   * output channel 0 is sqrt(1 + sum_o osp^2)  -> w_time_output is DEAD.
//   * osp[b,g,h,w,o] = t(b,h,w)*wti[o+1] + sum_d ps[b,hw,d] * Wt[g,o,d]
//       ps[d]  : d = kp*64 + cp  ->  x[b, h+dy(kp), w+dx(kp), 1+cp]   (0-pad)
//       Wt[g,o,d]: d = cw*9 + kw ->  rot90^g(weight_space[o, cw])[kw]
//     (flat-index pairing, exactly as the reference einsum does)
//   * t(b,h,w) = sqrt( sum_{3x3 nb} max(x[...,0], 1)^2 - 8 )   (pad -> 1)
//
// Kernel 0: pack weights into g_Wg[d][m],  m = g*64 + o   (9*64*256 fp32)
// Kernel 1: implicit GEMM  M=256, N=64/block (one image row), K=576 in 18x32
// ============================================================================

__device__ __align__(16) float g_Wg[9 * 64 * 256];

__global__ void build_weights_kernel(const float* __restrict__ ws) {
    int idx = blockIdx.x * 256 + threadIdx.x;
    if (idx >= 9 * 64 * 256) return;
    int m = idx & 255;   // g*64 + o
    int d = idx >> 8;    // 0..575
    int g = m >> 6;
    int o = m & 63;
    int cw = d / 9;
    int kw = d - cw * 9;
    int i = kw / 3, j = kw - (kw / 3) * 3;
    int i2, j2;
    // numpy rot90 applied g times (CCW): rot90(A)[i,j] = A[j, 2-i]
    switch (g) {
        case 0:  i2 = i;     j2 = j;     break;
        case 1:  i2 = j;     j2 = 2 - i; break;
        case 2:  i2 = 2 - i; j2 = 2 - j; break;
        default: i2 = 2 - j; j2 = i;     break;
    }
    g_Wg[d * 256 + m] = ws[(o * 64 + cw) * 9 + i2 * 3 + j2];
}

__global__ __launch_bounds__(256, 2) void lorentz_main_kernel(
    const float* __restrict__ x,     // (16,64,64,65)
    const float* __restrict__ wti,   // (65,1)
    float* __restrict__ out)         // (16,4,64,64,65)
{
    __shared__ __align__(16) float As[32][256];  // [kk][m]
    __shared__ float Bs[64][32];                 // [n][kk]
    __shared__ float ts[64];

    const int blk = blockIdx.x;
    const int b = blk >> 6;
    const int h = blk & 63;
    const int tid = threadIdx.x;
    const int tm = tid & 31;   // M lane (fast within warp -> coalesced stores)
    const int tn = tid >> 5;   // N group 0..7 (constant per warp -> LDS bcast)

    // ---- time component t(b,h,w) for the 64 pixels of this row ----
    if (tid < 64) {
        int w = tid;
        float s = 0.f;
        #pragma unroll
        for (int dy = -1; dy <= 1; dy++) {
            int hh = h + dy;
            #pragma unroll
            for (int dx = -1; dx <= 1; dx++) {
                int ww = w + dx;
                float v = 0.f;
                if (hh >= 0 && hh < 64 && ww >= 0 && ww < 64)
                    v = x[((size_t)(b * 64 + hh) * 64 + ww) * 65];
                v = fmaxf(v, 1.0f);
                s = fmaf(v, v, s);
            }
        }
        ts[w] = sqrtf(s - 8.0f);
    }

    // per-thread time-input weights: m = mi*32 + tm, o = m & 63, use wti[o+1]
    float wtir[8];
    #pragma unroll
    for (int mi = 0; mi < 8; mi++)
        wtir[mi] = wti[((mi * 32 + tm) & 63) + 1];

    __syncthreads();

    // accumulators initialized with the rank-1 time term
    float acc[8][8];
    #pragma unroll
    for (int mi = 0; mi < 8; mi++) {
        #pragma unroll
        for (int nj = 0; nj < 8; nj++)
            acc[mi][nj] = ts[nj * 8 + tn] * wtir[mi];
    }

    const int lc  = tid & 31;        // B-load: channel within 32-half
    const int lnb = (tid >> 5) * 8;  // B-load: pixel base

    // ---- main loop: 9 conv taps x 2 channel-halves (K-slices of 32) ----
    for (int kp = 0; kp < 9; kp++) {
        const int dy = kp / 3 - 1;
        const int dx = kp - (kp / 3) * 3 - 1;
        const int hh = h + dy;
        const bool rowok = (hh >= 0 && hh < 64);
        const float* xrow = x + (size_t)(b * 64 + (rowok ? hh : 0)) * 64 * 65;

        for (int half = 0; half < 2; half++) {
            __syncthreads();  // previous slice fully consumed

            // A slice: contiguous 8 KB of packed weights, float4-coalesced
            {
                const float4* src =
                    (const float4*)(g_Wg + (size_t)(kp * 64 + half * 32) * 256);
                float4* dst = (float4*)&As[0][0];
                #pragma unroll
                for (int i = 0; i < 8; i++)
                    dst[tid + i * 256] = src[tid + i * 256];
            }
            // B slice: x channels [1+half*32, 1+half*32+32) for 64 shifted pixels
            #pragma unroll
            for (int r = 0; r < 8; r++) {
                int n = lnb + r;
                int ww = n + dx;
                float v = 0.f;
                if (rowok && ww >= 0 && ww < 64)
                    v = xrow[(size_t)ww * 65 + 1 + half * 32 + lc];
                Bs[n][lc] = v;  // lanes write consecutive -> conflict-free
            }
            __syncthreads();

            #pragma unroll 4
            for (int kk = 0; kk < 32; kk++) {
                float a[8], bv[8];
                #pragma unroll
                for (int mi = 0; mi < 8; mi++)
                    a[mi] = As[kk][mi * 32 + tm];       // lanes consecutive
                #pragma unroll
                for (int nj = 0; nj < 8; nj++)
                    bv[nj] = Bs[nj * 8 + tn][kk];       // warp broadcast
                #pragma unroll
                for (int mi = 0; mi < 8; mi++) {
                    #pragma unroll
                    for (int nj = 0; nj < 8; nj++)
                        acc[mi][nj] = fmaf(a[mi], bv[nj], acc[mi][nj]);
                }
            }
        }
    }

    // ---- epilogue: Lorentz norm per (g, pixel) via warp shuffle, then store ----
    // rows: mi=2g   -> o = tm       (m = g*64 + tm)
    //       mi=2g+1 -> o = 32 + tm  (m = g*64 + 32 + tm)
    #pragma unroll
    for (int g = 0; g < 4; g++) {
        #pragma unroll
        for (int nj = 0; nj < 8; nj++) {
            float v0 = acc[2 * g][nj];
            float v1 = acc[2 * g + 1][nj];
            float p = fmaf(v0, v0, v1 * v1);
            #pragma unroll
            for (int off = 16; off; off >>= 1)
                p += __shfl_xor_sync(0xffffffffu, p, off);
            int n = nj * 8 + tn;
            float* orow = out + (((size_t)(b * 4 + g) * 64 + h) * 64 + n) * 65;
            if (tm == 0) orow[0] = sqrtf(1.0f + p);
            orow[1 + tm]  = v0;   // lanes consecutive -> 128B coalesced
            orow[33 + tm] = v1;
        }
    }
}

extern "C" void kernel_launch(void* const* d_in, const int* in_sizes, int n_in,
                              void* d_out, int out_size) {
    const float* x   = (const float*)d_in[0];  // (16,64,64,65)
    const float* ws  = (const float*)d_in[1];  // (64,64,1,3,3)
    // d_in[2] = w_time_output : dead (its output row is discarded by the ref)
    const float* wti = (const float*)d_in[3];  // (65,1)
    float* out = (float*)d_out;

    build_weights_kernel<<<(9 * 64 * 256 + 255) / 256, 256>>>(ws);
    lorentz_main_kernel<<<16 * 64, 256>>>(x, wti, out);
}

// round 2
// speedup vs baseline: 1.0244x; 1.0244x over previous
#include <cuda_runtime.h>
#include <math.h>

// ============================================================================
// GroupLorentzConv2d — fp32x2 (FFMA2) implicit-GEMM version.
//   M=256 (4 rot x 64 oc), N=64 pixels/block (one image row), K=576 (9 taps x 64 ch)
//   Accumulators packed as f32x2 pairs (m, m+128); fma.rn.f32x2 inner loop.
//   A tile double-buffered via cp.async; B prefetched to regs one slice ahead.
// ============================================================================

typedef unsigned long long u64;

// packed weights, slice-major: g_Wg2[d*256 + 2*p + s] = W(d, p + 128*s),
//   W(d, m): m = g*64+o, d = cw*9+kw, value = rot90^g(ws[o, cw])[kw]
__device__ __align__(16) float g_Wg2[576 * 256];

__global__ void build_weights_kernel(const float* __restrict__ ws) {
    int idx = blockIdx.x * 256 + threadIdx.x;
    if (idx >= 576 * 256) return;
    int q = idx & 255;          // 2*p + s
    int d = idx >> 8;           // 0..575
    int p = q >> 1;
    int s = q & 1;
    int m = p + 128 * s;
    int g = m >> 6, o = m & 63;
    int cw = d / 9, kw = d - cw * 9;
    int i = kw / 3, j = kw - (kw / 3) * 3;
    int i2, j2;
    // numpy rot90 applied g times (CCW): rot90(A)[i,j] = A[j, 2-i]
    switch (g) {
        case 0:  i2 = i;     j2 = j;     break;
        case 1:  i2 = j;     j2 = 2 - i; break;
        case 2:  i2 = 2 - i; j2 = 2 - j; break;
        default: i2 = 2 - j; j2 = i;     break;
    }
    g_Wg2[d * 256 + q] = ws[(o * 64 + cw) * 9 + i2 * 3 + j2];
}

// dynamic smem layout:
//   [0, 65536)          As : float[2][32][256]   (double-buffered A slice)
//   [65536, 81920)      Bsd: u64[64][32]         (B duplicated (v,v) pairs)
//   [81920, 82176)      ts : float[64]
#define SMEM_BYTES (65536 + 16384 + 256)

__global__ void __launch_bounds__(256, 2) lorentz_main_kernel(
    const float* __restrict__ x,     // (16,64,64,65)
    const float* __restrict__ wti,   // (65,1)
    float* __restrict__ out)         // (16,4,64,64,65)
{
    extern __shared__ __align__(16) char dsmem[];
    float* As = (float*)dsmem;
    u64*  Bsd = (u64*)(dsmem + 65536);
    float* ts = (float*)(dsmem + 65536 + 16384);

    const int blk = blockIdx.x;
    const int b = blk >> 6;
    const int h = blk & 63;
    const int tid = threadIdx.x;
    const int tm  = tid & 31;      // M lane (coalesced epilogue stores)
    const int tn  = tid >> 5;      // N group 0..7 (warp-constant -> LDS bcast)
    const int lc  = tid & 31;      // loader: channel lane
    const int lnb = (tid >> 5) * 8;// loader: pixel base

    const unsigned sA = (unsigned)__cvta_generic_to_shared(As);

    // ---- helpers ----------------------------------------------------------
    auto issueA = [&](int sl, int buf) {
        const float* src = g_Wg2 + sl * 8192 + tid * 4;
        unsigned dst = sA + buf * 32768 + tid * 16;
        #pragma unroll
        for (int j = 0; j < 8; j++)
            asm volatile("cp.async.cg.shared.global [%0], [%1], 16;\n"
                         :: "r"(dst + j * 4096), "l"(src + j * 1024));
        asm volatile("cp.async.commit_group;\n");
    };
    auto loadB = [&](int sl, float* v) {
        int kp = sl >> 1, half = sl & 1;
        int dy = kp / 3 - 1, dx = kp - (kp / 3) * 3 - 1;
        int hh = h + dy;
        bool rowok = (hh >= 0 && hh < 64);
        const float* xr = x + (size_t)(b * 64 + (rowok ? hh : 0)) * 64 * 65
                            + 1 + half * 32 + lc;
        #pragma unroll
        for (int r = 0; r < 8; r++) {
            int ww = lnb + r + dx;
            v[r] = (rowok && ww >= 0 && ww < 64) ? xr[(size_t)ww * 65] : 0.f;
        }
    };
    auto storeB = [&](const float* v) {
        #pragma unroll
        for (int r = 0; r < 8; r++) {
            float2 p2 = make_float2(v[r], v[r]);
            Bsd[(lnb + r) * 32 + lc] = *reinterpret_cast<u64*>(&p2);
        }
    };

    // ---- prologue ---------------------------------------------------------
    float Breg[8];
    loadB(0, Breg);
    issueA(0, 0);

    // time component t(b,h,w) for the 64 pixels of this row
    if (tid < 64) {
        int w = tid;
        float s = 0.f;
        #pragma unroll
        for (int dy = -1; dy <= 1; dy++) {
            int hh = h + dy;
            #pragma unroll
            for (int dx = -1; dx <= 1; dx++) {
                int ww = w + dx;
                float v = 0.f;
                if (hh >= 0 && hh < 64 && ww >= 0 && ww < 64)
                    v = x[((size_t)(b * 64 + hh) * 64 + ww) * 65];
                v = fmaxf(v, 1.0f);
                s = fmaf(v, v, s);
            }
        }
        ts[w] = sqrtf(s - 8.0f);
    }

    // time-input weights: both halves of a pair share o = (32i+tm)&63
    float wv[4];
    #pragma unroll
    for (int i = 0; i < 4; i++)
        wv[i] = wti[((i * 32 + tm) & 63) + 1];

    asm volatile("cp.async.wait_group 0;\n" ::: "memory");
    __syncthreads();                 // As buf0 + ts visible

    storeB(Breg);                    // Bsd(slice 0)
    loadB(1, Breg);

    // accumulators = rank-1 time term (same value in both f32x2 halves)
    u64 acc[4][8];
    #pragma unroll
    for (int i = 0; i < 4; i++) {
        #pragma unroll
        for (int j = 0; j < 8; j++) {
            float t0 = ts[j * 8 + tn] * wv[i];
            float2 p2 = make_float2(t0, t0);
            acc[i][j] = *reinterpret_cast<u64*>(&p2);
        }
    }
    __syncthreads();                 // Bsd(0) ready

    // ---- main loop: 18 K-slices of 32 -------------------------------------
    for (int sl = 0; sl < 18; sl++) {
        if (sl < 17) issueA(sl + 1, (sl + 1) & 1);
        const float* Ab = As + (sl & 1) * 8192;

        #pragma unroll 4
        for (int kk = 0; kk < 32; kk++) {
            u64 a2[4], b2[8];
            #pragma unroll
            for (int i = 0; i < 4; i++)
                a2[i] = *reinterpret_cast<const u64*>(Ab + kk * 256 + 2 * (tm + 32 * i));
            #pragma unroll
            for (int j = 0; j < 8; j++)
                b2[j] = Bsd[(j * 8 + tn) * 32 + kk];
            #pragma unroll
            for (int i = 0; i < 4; i++) {
                #pragma unroll
                for (int j = 0; j < 8; j++)
                    asm("fma.rn.f32x2 %0, %1, %2, %0;"
                        : "+l"(acc[i][j]) : "l"(a2[i]), "l"(b2[j]));
            }
        }

        __syncthreads();             // all warps done with Bsd (and this A buf)
        if (sl < 17) {
            storeB(Breg);            // Bsd(sl+1)
            if (sl < 16) loadB(sl + 2, Breg);
            asm volatile("cp.async.wait_group 0;\n" ::: "memory");
            __syncthreads();         // As(sl+1) + Bsd(sl+1) ready
        }
    }

    // ---- epilogue: Lorentz norm per (g, pixel), coalesced stores ----------
    // pair i: lo half -> m = 32i+tm, hi half -> m = 32i+128+tm
    #pragma unroll
    for (int g = 0; g < 4; g++) {
        const int ib = (g & 1) * 2;
        const bool hiH = (g >= 2);
        #pragma unroll
        for (int j = 0; j < 8; j++) {
            float lo0, hi0, lo1, hi1;
            asm("mov.b64 {%0,%1}, %2;" : "=f"(lo0), "=f"(hi0) : "l"(acc[ib][j]));
            asm("mov.b64 {%0,%1}, %2;" : "=f"(lo1), "=f"(hi1) : "l"(acc[ib + 1][j]));
            float v0 = hiH ? hi0 : lo0;   // o = tm
            float v1 = hiH ? hi1 : lo1;   // o = 32 + tm
            float p = fmaf(v0, v0, v1 * v1);
            #pragma unroll
            for (int off = 16; off; off >>= 1)
                p += __shfl_xor_sync(0xffffffffu, p, off);
            int n = j * 8 + tn;
            float* orow = out + (((size_t)(b * 4 + g) * 64 + h) * 64 + n) * 65;
            if (tm == 0) orow[0] = sqrtf(1.0f + p);
            orow[1 + tm]  = v0;
            orow[33 + tm] = v1;
        }
    }
}

extern "C" void kernel_launch(void* const* d_in, const int* in_sizes, int n_in,
                              void* d_out, int out_size) {
    const float* x   = (const float*)d_in[0];  // (16,64,64,65)
    const float* ws  = (const float*)d_in[1];  // (64,64,1,3,3)
    // d_in[2] = w_time_output : dead (its output row is discarded by the ref)
    const float* wti = (const float*)d_in[3];  // (65,1)
    float* out = (float*)d_out;

    cudaFuncSetAttribute(lorentz_main_kernel,
                         cudaFuncAttributeMaxDynamicSharedMemorySize, SMEM_BYTES);

    build_weights_kernel<<<576, 256>>>(ws);
    lorentz_main_kernel<<<16 * 64, 256, SMEM_BYTES>>>(x, wti, out);
}

// round 6
// speedup vs baseline: 3.9839x; 3.8889x over previous
#include <cuda_runtime.h>
#include <math.h>
#include <stdint.h>

// ============================================================================
// GroupLorentzConv2d via legacy tensor-core path (mma.sync tf32, sm_80 PTX —
// compiles under compute_100, runs on B200 HMMA).
//
//   C[p, n] = sum_d A[p,d] * W[n,d] + t(p)*wti[(n&63)+1],  n = g*64 + o
//   Flat-index pairing (as the reference einsum):
//     A side: d = kp*64 + cp  -> x[b, h+dy(kp), w+dx(kp), 1+cp]
//     W side: d = cw*9  + kw  -> rot90^g(weight_space[o, cw])[kw]
//   K = 576 = 18 chunks x 32 (d-chunks; A side = 9 taps x 2 channel-halves)
//   out[b,g,h,w,0]   = sqrt(1 + sum_o C[p, g*64+o]^2)
//   out[b,g,h,w,1+o] = C[p, g*64+o]
//
// CTA: 128 pixels (2 image rows) x 128 outputs (n-half = 2 rotation groups)
// 8 warps, warp tile 32(px) x 64(out). cp.async double-buffered K-chunks,
// ldmatrix.x4 fragment loads on XOR-swizzled tiles.
// ============================================================================

typedef uint32_t u32;

__device__ __align__(16) float g_xpad[16 * 64 * 64 * 64]; // tf32 (b,h,w,c) c-fast
__device__ __align__(16) float g_Wt[18 * 256 * 32];       // tf32 [chunk][n][kc]
__device__ float g_tmap[16 * 64 * 64];

__device__ __forceinline__ float to_tf32(float v) {
    u32 r;                                   // tf32 cvt needs .b32 destination
    asm("cvt.rna.tf32.f32 %0, %1;" : "=r"(r) : "f"(v));
    return __uint_as_float(r);
}

// ---------------- prep kernels ----------------------------------------------
__global__ void prep_xpad(const float* __restrict__ x) {
    int i = blockIdx.x * 256 + threadIdx.x;
    if (i >= 16 * 64 * 64 * 64) return;
    int c = i & 63, pix = i >> 6;
    g_xpad[i] = to_tf32(x[(size_t)pix * 65 + 1 + c]);
}

__global__ void prep_tmap(const float* __restrict__ x) {
    int i = blockIdx.x * 256 + threadIdx.x;
    if (i >= 16 * 64 * 64) return;
    int w = i & 63, h = (i >> 6) & 63, b = i >> 12;
    float s = 0.f;
    #pragma unroll
    for (int dy = -1; dy <= 1; dy++) {
        int hh = h + dy;
        #pragma unroll
        for (int dx = -1; dx <= 1; dx++) {
            int ww = w + dx;
            float v = 0.f;
            if (hh >= 0 && hh < 64 && ww >= 0 && ww < 64)
                v = x[((size_t)(b * 64 + hh) * 64 + ww) * 65];
            v = fmaxf(v, 1.0f);
            s = fmaf(v, v, s);
        }
    }
    g_tmap[i] = sqrtf(s - 8.0f);
}

__global__ void prep_weights(const float* __restrict__ ws) {
    int i = blockIdx.x * 256 + threadIdx.x;   // [chunk][n][kc]
    if (i >= 18 * 256 * 32) return;
    int kc = i & 31;
    int n  = (i >> 5) & 255;
    int ch = i >> 13;
    int kp = ch >> 1, hf = ch & 1;
    int g = n >> 6, o = n & 63;
    // flat contraction index (tap-major on the A side):
    int d  = kp * 64 + hf * 32 + kc;
    // weight-side decomposition of the SAME flat d (channel-major):
    int cw = d / 9, kw = d - cw * 9;
    int r = kw / 3, cc = kw - r * 3;
    int i2, j2;
    switch (g) {                  // numpy rot90^g (CCW): rot90(A)[i,j] = A[j, 2-i]
        case 0:  i2 = r;      j2 = cc;     break;
        case 1:  i2 = cc;     j2 = 2 - r;  break;
        case 2:  i2 = 2 - r;  j2 = 2 - cc; break;
        default: i2 = 2 - cc; j2 = r;      break;
    }
    g_Wt[i] = to_tf32(ws[(o * 64 + cw) * 9 + i2 * 3 + j2]);
}

// ---------------- main kernel ------------------------------------------------
// smem: A tiles [2][128][32] @0 (32KB), B tiles [2][128][32] @32KB (32KB)
//       stage float[2][128][65] @0 (66,560B) — overlaps tiles (used after loop)
#define SM_A 0
#define SM_B 32768
#define SMEM_BYTES 66560

__device__ __forceinline__ void cp16(u32 dst, const void* src, int sz) {
    asm volatile("cp.async.cg.shared.global [%0], [%1], 16, %2;"
                 :: "r"(dst), "l"(src), "r"(sz));
}
__device__ __forceinline__ void ldm4(u32* r, u32 addr) {
    asm volatile("ldmatrix.sync.aligned.m8n8.x4.shared.b16 {%0,%1,%2,%3}, [%4];"
                 : "=r"(r[0]), "=r"(r[1]), "=r"(r[2]), "=r"(r[3]) : "r"(addr));
}
__device__ __forceinline__ void mma8(float* c, const u32* a, const u32* b) {
    asm volatile(
        "mma.sync.aligned.m16n8k8.row.col.f32.tf32.tf32.f32 "
        "{%0,%1,%2,%3}, {%4,%5,%6,%7}, {%8,%9}, {%0,%1,%2,%3};"
        : "+f"(c[0]), "+f"(c[1]), "+f"(c[2]), "+f"(c[3])
        : "r"(a[0]), "r"(a[1]), "r"(a[2]), "r"(a[3]), "r"(b[0]), "r"(b[1]));
}

__global__ void __launch_bounds__(256, 2) lorentz_mma_kernel(
    const float* __restrict__ wti,   // (65,1)
    float* __restrict__ out)         // (16,4,64,64,65)
{
    extern __shared__ __align__(16) char sm[];
    const int tid  = threadIdx.x;
    const int lane = tid & 31, wid = tid >> 5;
    const int wm = wid & 3;          // pixel-warp 0..3  (32 px each)
    const int wn = wid >> 2;         // out-warp 0..1    (64 out each = one g)
    const int bid = blockIdx.x;
    const int nh  = bid & 1;         // n-half: outputs [nh*128, nh*128+128)
    const int mt_ = bid >> 1;
    const int b   = mt_ >> 5;
    const int h0  = (mt_ & 31) << 1; // rows h0, h0+1

    const u32 smb = (u32)__cvta_generic_to_shared(sm);

    // ---- cp.async tile loaders (XOR-swizzled, zero-fill OOB) ----
    auto loadA = [&](int ch, int s) {
        const int kp = ch >> 1, hf = ch & 1;
        const int dy = kp / 3 - 1, dx = kp - (kp / 3) * 3 - 1;
        #pragma unroll
        for (int it = 0; it < 4; it++) {
            int idx = tid + it * 256;        // 128 px x 8 vec
            int p = idx >> 3, v = idx & 7;
            int hh = h0 + (p >> 6) + dy, ww = (p & 63) + dx;
            bool ok = (hh >= 0 && hh < 64 && ww >= 0 && ww < 64);
            const float* src = g_xpad +
                ((size_t)((b * 64 + (ok ? hh : 0)) * 64 + (ok ? ww : 0))) * 64 +
                hf * 32 + v * 4;
            cp16(smb + SM_A + s * 16384 + p * 128 + ((v ^ (p & 7)) << 4),
                 src, ok ? 16 : 0);
        }
    };
    auto loadB = [&](int ch, int s) {
        const float* base = g_Wt + ch * 8192 + nh * 4096;
        #pragma unroll
        for (int it = 0; it < 4; it++) {
            int idx = tid + it * 256;        // 128 n x 8 vec
            int n = idx >> 3, v = idx & 7;
            cp16(smb + SM_B + s * 16384 + n * 128 + ((v ^ (n & 7)) << 4),
                 base + idx * 4, 16);
        }
    };

    loadA(0, 0); loadB(0, 0);
    asm volatile("cp.async.commit_group;");
    loadA(1, 1); loadB(1, 1);
    asm volatile("cp.async.commit_group;");

    // ---- accumulator init: exact-fp32 rank-1 time term ----
    float tv[2][2];
    #pragma unroll
    for (int mt = 0; mt < 2; mt++)
        #pragma unroll
        for (int rr = 0; rr < 2; rr++) {
            int p = wm * 32 + mt * 16 + rr * 8 + (lane >> 2);
            tv[mt][rr] = g_tmap[(size_t)(b * 64 + h0 + (p >> 6)) * 64 + (p & 63)];
        }
    float acc[2][8][4];
    #pragma unroll
    for (int nt = 0; nt < 8; nt++) {
        float w0 = wti[1 + nt * 8 + 2 * (lane & 3)];
        float w1 = wti[2 + nt * 8 + 2 * (lane & 3)];
        #pragma unroll
        for (int mt = 0; mt < 2; mt++) {
            acc[mt][nt][0] = tv[mt][0] * w0;
            acc[mt][nt][1] = tv[mt][0] * w1;
            acc[mt][nt][2] = tv[mt][1] * w0;
            acc[mt][nt][3] = tv[mt][1] * w1;
        }
    }

    // ---- main loop: 18 K-chunks of 32, double-buffered ----
    const int grp = lane >> 3, lr = lane & 7;
    const int am  = wm * 32 + lr + ((grp & 1) << 3);  // + mt*16
    const int bn  = wn * 64 + lr + ((grp >> 1) << 3); // + bt*16
    const int akv = grp >> 1;                         // + 2*ks
    const int bkv = grp & 1;

    for (int c = 0; c < 18; c++) {
        const int s = c & 1;
        if (c < 17) asm volatile("cp.async.wait_group 1;" ::: "memory");
        else        asm volatile("cp.async.wait_group 0;" ::: "memory");
        __syncthreads();

        const u32 Ab = smb + SM_A + s * 16384;
        const u32 Bb = smb + SM_B + s * 16384;

        #pragma unroll
        for (int ks = 0; ks < 4; ks++) {
            u32 af[2][4];
            #pragma unroll
            for (int mt = 0; mt < 2; mt++) {
                int m = am + mt * 16;
                ldm4(af[mt], Ab + m * 128 + (((2 * ks + akv) ^ (m & 7)) << 4));
            }
            u32 bf[4][4];
            #pragma unroll
            for (int bt = 0; bt < 4; bt++) {
                int n = bn + bt * 16;
                ldm4(bf[bt], Bb + n * 128 + (((2 * ks + bkv) ^ (n & 7)) << 4));
            }
            #pragma unroll
            for (int mt = 0; mt < 2; mt++)
                #pragma unroll
                for (int nt = 0; nt < 8; nt++)
                    mma8(acc[mt][nt], af[mt], &bf[nt >> 1][(nt & 1) * 2]);
        }

        __syncthreads();
        if (c + 2 < 18) {
            loadA(c + 2, s); loadB(c + 2, s);
            asm volatile("cp.async.commit_group;");
        }
    }

    // ---- epilogue: per-(g,pixel) Lorentz norm + staged coalesced stores ----
    __syncthreads();                         // stage aliases the tiles
    float* stage = (float*)sm;               // [gg][128][65]
    float* stg = stage + wn * 8320;

    #pragma unroll
    for (int mt = 0; mt < 2; mt++) {
        #pragma unroll
        for (int rr = 0; rr < 2; rr++) {
            float ssum = 0.f;
            #pragma unroll
            for (int nt = 0; nt < 8; nt++) {
                float v0 = acc[mt][nt][rr * 2];
                float v1 = acc[mt][nt][rr * 2 + 1];
                ssum = fmaf(v0, v0, fmaf(v1, v1, ssum));
            }
            ssum += __shfl_xor_sync(0xffffffffu, ssum, 1);
            ssum += __shfl_xor_sync(0xffffffffu, ssum, 2);
            int p = wm * 32 + mt * 16 + rr * 8 + (lane >> 2);
            float* row = stg + p * 65;
            if ((lane & 3) == 0) row[0] = sqrtf(1.f + ssum);
            #pragma unroll
            for (int nt = 0; nt < 8; nt++) {
                row[1 + nt * 8 + 2 * (lane & 3)] = acc[mt][nt][rr * 2];
                row[2 + nt * 8 + 2 * (lane & 3)] = acc[mt][nt][rr * 2 + 1];
            }
        }
    }
    __syncthreads();

    #pragma unroll
    for (int gg = 0; gg < 2; gg++) {
        int g = nh * 2 + gg;
        float4* dst = (float4*)(out + ((size_t)(b * 4 + g) * 64 + h0) * 64 * 65);
        const float4* src = (const float4*)(stage + gg * 8320);
        for (int i = tid; i < 2080; i += 256) dst[i] = src[i];
    }
}

extern "C" void kernel_launch(void* const* d_in, const int* in_sizes, int n_in,
                              void* d_out, int out_size) {
    const float* x   = (const float*)d_in[0];  // (16,64,64,65)
    const float* ws  = (const float*)d_in[1];  // (64,64,1,3,3)
    // d_in[2] = w_time_output : dead (its output row is replaced by the norm)
    const float* wti = (const float*)d_in[3];  // (65,1)
    float* out = (float*)d_out;

    prep_xpad<<<(16 * 64 * 64 * 64 + 255) / 256, 256>>>(x);
    prep_tmap<<<(16 * 64 * 64 + 255) / 256, 256>>>(x);
    prep_weights<<<(18 * 256 * 32 + 255) / 256, 256>>>(ws);

    cudaFuncSetAttribute(lorentz_mma_kernel,
                         cudaFuncAttributeMaxDynamicSharedMemorySize, SMEM_BYTES);
    lorentz_mma_kernel<<<1024, 256, SMEM_BYTES>>>(wti, out);
}

// round 7
// speedup vs baseline: 4.0501x; 1.0166x over previous
#include <cuda_runtime.h>
#include <math.h>
#include <stdint.h>

// ============================================================================
// GroupLorentzConv2d via legacy tensor-core path (mma.sync tf32, sm_80 PTX —
// compiles under compute_100, runs on B200 HMMA).
//
//   C[p, n] = sum_d A[p,d] * W[n,d] + t(p)*wti[(n&63)+1],  n = g*64 + o
//   Flat-index pairing (as the reference einsum):
//     A side: d = kp*64 + cp  -> x[b, h+dy(kp), w+dx(kp), 1+cp]
//     W side: d = cw*9  + kw  -> rot90^g(weight_space[o, cw])[kw]
//   K = 576 = 18 chunks x 32 (d-chunks; A side = 9 taps x 2 channel-halves)
//   out[b,g,h,w,0]   = sqrt(1 + sum_o C[p, g*64+o]^2)
//   out[b,g,h,w,1+o] = C[p, g*64+o]
//
// CTA: 128 pixels (2 image rows) x 128 outputs (n-half = 2 rotation groups)
// 8 warps, warp tile 32(px) x 64(out). 3-stage cp.async ring (ONE barrier per
// K-chunk), ldmatrix.x4 fragment loads on XOR-swizzled tiles.
// ============================================================================

typedef uint32_t u32;

__device__ __align__(16) float g_xpad[16 * 64 * 64 * 64]; // tf32 (b,h,w,c) c-fast
__device__ __align__(16) float g_Wt[18 * 256 * 32];       // tf32 [chunk][n][kc]
__device__ float g_tmap[16 * 64 * 64];

__device__ __forceinline__ float to_tf32(float v) {
    u32 r;                                   // tf32 cvt needs .b32 destination
    asm("cvt.rna.tf32.f32 %0, %1;" : "=r"(r) : "f"(v));
    return __uint_as_float(r);
}

// ---------------- fused prep kernel -----------------------------------------
// blocks [0, 16384)            : xpad   (4.19M elems)
// blocks [16384, 16384+256)    : tmap   (65536 elems)
// blocks [16640, 16640+576)    : weights(147456 elems)
__global__ void prep_all(const float* __restrict__ x,
                         const float* __restrict__ ws) {
    int blk = blockIdx.x;
    if (blk < 16384) {
        int i = blk * 256 + threadIdx.x;
        int c = i & 63, pix = i >> 6;
        g_xpad[i] = to_tf32(x[(size_t)pix * 65 + 1 + c]);
        return;
    }
    if (blk < 16640) {
        int i = (blk - 16384) * 256 + threadIdx.x;
        int w = i & 63, h = (i >> 6) & 63, b = i >> 12;
        float s = 0.f;
        #pragma unroll
        for (int dy = -1; dy <= 1; dy++) {
            int hh = h + dy;
            #pragma unroll
            for (int dx = -1; dx <= 1; dx++) {
                int ww = w + dx;
                float v = 0.f;
                if (hh >= 0 && hh < 64 && ww >= 0 && ww < 64)
                    v = x[((size_t)(b * 64 + hh) * 64 + ww) * 65];
                v = fmaxf(v, 1.0f);
                s = fmaf(v, v, s);
            }
        }
        g_tmap[i] = sqrtf(s - 8.0f);
        return;
    }
    {
        int i = (blk - 16640) * 256 + threadIdx.x;   // [chunk][n][kc]
        if (i >= 18 * 256 * 32) return;
        int kc = i & 31;
        int n  = (i >> 5) & 255;
        int ch = i >> 13;
        int kp = ch >> 1, hf = ch & 1;
        int g = n >> 6, o = n & 63;
        int d  = kp * 64 + hf * 32 + kc;     // flat index, tap-major (A side)
        int cw = d / 9, kw = d - cw * 9;     // same d, channel-major (W side)
        int r = kw / 3, cc = kw - r * 3;
        int i2, j2;
        switch (g) {              // numpy rot90^g (CCW): rot90(A)[i,j] = A[j, 2-i]
            case 0:  i2 = r;      j2 = cc;     break;
            case 1:  i2 = cc;     j2 = 2 - r;  break;
            case 2:  i2 = 2 - r;  j2 = 2 - cc; break;
            default: i2 = 2 - cc; j2 = r;      break;
        }
        g_Wt[i] = to_tf32(ws[(o * 64 + cw) * 9 + i2 * 3 + j2]);
    }
}

// ---------------- main kernel ------------------------------------------------
// smem: ring of 3 stages, each {A [128][32] 16KB, B [128][32] 16KB} = 96 KB
//       stage float[2][128][65] @0 (66,560B) — aliases ring (used after loop)
#define SM_A 0
#define SM_B 49152                 // B stages start after 3 A stages
#define SMEM_BYTES 98304

__device__ __forceinline__ void cp16(u32 dst, const void* src, int sz) {
    asm volatile("cp.async.cg.shared.global [%0], [%1], 16, %2;"
                 :: "r"(dst), "l"(src), "r"(sz));
}
__device__ __forceinline__ void ldm4(u32* r, u32 addr) {
    asm volatile("ldmatrix.sync.aligned.m8n8.x4.shared.b16 {%0,%1,%2,%3}, [%4];"
                 : "=r"(r[0]), "=r"(r[1]), "=r"(r[2]), "=r"(r[3]) : "r"(addr));
}
__device__ __forceinline__ void mma8(float* c, const u32* a, const u32* b) {
    asm volatile(
        "mma.sync.aligned.m16n8k8.row.col.f32.tf32.tf32.f32 "
        "{%0,%1,%2,%3}, {%4,%5,%6,%7}, {%8,%9}, {%0,%1,%2,%3};"
        : "+f"(c[0]), "+f"(c[1]), "+f"(c[2]), "+f"(c[3])
        : "r"(a[0]), "r"(a[1]), "r"(a[2]), "r"(a[3]), "r"(b[0]), "r"(b[1]));
}

__global__ void __launch_bounds__(256, 2) lorentz_mma_kernel(
    const float* __restrict__ wti,   // (65,1)
    float* __restrict__ out)         // (16,4,64,64,65)
{
    extern __shared__ __align__(16) char sm[];
    const int tid  = threadIdx.x;
    const int lane = tid & 31, wid = tid >> 5;
    const int wm = wid & 3;          // pixel-warp 0..3  (32 px each)
    const int wn = wid >> 2;         // out-warp 0..1    (64 out each = one g)
    const int bid = blockIdx.x;
    const int nh  = bid & 1;         // n-half: outputs [nh*128, nh*128+128)
    const int mt_ = bid >> 1;
    const int b   = mt_ >> 5;
    const int h0  = (mt_ & 31) << 1; // rows h0, h0+1

    const u32 smb = (u32)__cvta_generic_to_shared(sm);

    // ---- cp.async tile loaders (XOR-swizzled, zero-fill OOB) ----
    auto loadA = [&](int ch, int s) {
        const int kp = ch >> 1, hf = ch & 1;
        const int dy = kp / 3 - 1, dx = kp - (kp / 3) * 3 - 1;
        #pragma unroll
        for (int it = 0; it < 4; it++) {
            int idx = tid + it * 256;        // 128 px x 8 vec
            int p = idx >> 3, v = idx & 7;
            int hh = h0 + (p >> 6) + dy, ww = (p & 63) + dx;
            bool ok = (hh >= 0 && hh < 64 && ww >= 0 && ww < 64);
            const float* src = g_xpad +
                ((size_t)((b * 64 + (ok ? hh : 0)) * 64 + (ok ? ww : 0))) * 64 +
                hf * 32 + v * 4;
            cp16(smb + SM_A + s * 16384 + p * 128 + ((v ^ (p & 7)) << 4),
                 src, ok ? 16 : 0);
        }
    };
    auto loadB = [&](int ch, int s) {
        const float* base = g_Wt + ch * 8192 + nh * 4096;
        #pragma unroll
        for (int it = 0; it < 4; it++) {
            int idx = tid + it * 256;        // 128 n x 8 vec
            int n = idx >> 3, v = idx & 7;
            cp16(smb + SM_B + s * 16384 + n * 128 + ((v ^ (n & 7)) << 4),
                 base + idx * 4, 16);
        }
    };

    loadA(0, 0); loadB(0, 0);
    asm volatile("cp.async.commit_group;");
    loadA(1, 1); loadB(1, 1);
    asm volatile("cp.async.commit_group;");

    // ---- accumulator init: exact-fp32 rank-1 time term ----
    float tv[2][2];
    #pragma unroll
    for (int mt = 0; mt < 2; mt++)
        #pragma unroll
        for (int rr = 0; rr < 2; rr++) {
            int p = wm * 32 + mt * 16 + rr * 8 + (lane >> 2);
            tv[mt][rr] = g_tmap[(size_t)(b * 64 + h0 + (p >> 6)) * 64 + (p & 63)];
        }
    float acc[2][8][4];
    #pragma unroll
    for (int nt = 0; nt < 8; nt++) {
        float w0 = wti[1 + nt * 8 + 2 * (lane & 3)];
        float w1 = wti[2 + nt * 8 + 2 * (lane & 3)];
        #pragma unroll
        for (int mt = 0; mt < 2; mt++) {
            acc[mt][nt][0] = tv[mt][0] * w0;
            acc[mt][nt][1] = tv[mt][0] * w1;
            acc[mt][nt][2] = tv[mt][1] * w0;
            acc[mt][nt][3] = tv[mt][1] * w1;
        }
    }

    // ---- main loop: 18 K-chunks of 32, 3-stage ring, ONE barrier/chunk ----
    const int grp = lane >> 3, lr = lane & 7;
    const int am  = wm * 32 + lr + ((grp & 1) << 3);  // + mt*16
    const int bn  = wn * 64 + lr + ((grp >> 1) << 3); // + bt*16
    const int akv = grp >> 1;                         // + 2*ks
    const int bkv = grp & 1;

    int s = 0;
    for (int c = 0; c < 18; c++, s = (s == 2) ? 0 : s + 1) {
        if (c < 17) asm volatile("cp.async.wait_group 1;" ::: "memory");
        else        asm volatile("cp.async.wait_group 0;" ::: "memory");
        __syncthreads();            // stage s ready; stage s-1 (== s+2) drained

        if (c + 2 < 18) {           // refill the buffer consumed at iter c-1
            int s2 = (s + 2 > 2) ? s - 1 : s + 2;
            loadA(c + 2, s2); loadB(c + 2, s2);
            asm volatile("cp.async.commit_group;");
        }

        const u32 Ab = smb + SM_A + s * 16384;
        const u32 Bb = smb + SM_B + s * 16384;

        #pragma unroll
        for (int ks = 0; ks < 4; ks++) {
            u32 af[2][4];
            #pragma unroll
            for (int mt = 0; mt < 2; mt++) {
                int m = am + mt * 16;
                ldm4(af[mt], Ab + m * 128 + (((2 * ks + akv) ^ (m & 7)) << 4));
            }
            u32 bf[4][4];
            #pragma unroll
            for (int bt = 0; bt < 4; bt++) {
                int n = bn + bt * 16;
                ldm4(bf[bt], Bb + n * 128 + (((2 * ks + bkv) ^ (n & 7)) << 4));
            }
            #pragma unroll
            for (int mt = 0; mt < 2; mt++)
                #pragma unroll
                for (int nt = 0; nt < 8; nt++)
                    mma8(acc[mt][nt], af[mt], &bf[nt >> 1][(nt & 1) * 2]);
        }
    }

    // ---- epilogue: per-(g,pixel) Lorentz norm + staged coalesced stores ----
    __syncthreads();                         // stage aliases the ring
    float* stage = (float*)sm;               // [gg][128][65]
    float* stg = stage + wn * 8320;

    #pragma unroll
    for (int mt = 0; mt < 2; mt++) {
        #pragma unroll
        for (int rr = 0; rr < 2; rr++) {
            float ssum = 0.f;
            #pragma unroll
            for (int nt = 0; nt < 8; nt++) {
                float v0 = acc[mt][nt][rr * 2];
                float v1 = acc[mt][nt][rr * 2 + 1];
                ssum = fmaf(v0, v0, fmaf(v1, v1, ssum));
            }
            ssum += __shfl_xor_sync(0xffffffffu, ssum, 1);
            ssum += __shfl_xor_sync(0xffffffffu, ssum, 2);
            int p = wm * 32 + mt * 16 + rr * 8 + (lane >> 2);
            float* row = stg + p * 65;
            if ((lane & 3) == 0) row[0] = sqrtf(1.f + ssum);
            #pragma unroll
            for (int nt = 0; nt < 8; nt++) {
                row[1 + nt * 8 + 2 * (lane & 3)] = acc[mt][nt][rr * 2];
                row[2 + nt * 8 + 2 * (lane & 3)] = acc[mt][nt][rr * 2 + 1];
            }
        }
    }
    __syncthreads();

    #pragma unroll
    for (int gg = 0; gg < 2; gg++) {
        int g = nh * 2 + gg;
        float4* dst = (float4*)(out + ((size_t)(b * 4 + g) * 64 + h0) * 64 * 65);
        const float4* src = (const float4*)(stage + gg * 8320);
        for (int i = tid; i < 2080; i += 256) dst[i] = src[i];
    }
}

extern "C" void kernel_launch(void* const* d_in, const int* in_sizes, int n_in,
                              void* d_out, int out_size) {
    const float* x   = (const float*)d_in[0];  // (16,64,64,65)
    const float* ws  = (const float*)d_in[1];  // (64,64,1,3,3)
    // d_in[2] = w_time_output : dead (its output row is replaced by the norm)
    const float* wti = (const float*)d_in[3];  // (65,1)
    float* out = (float*)d_out;

    prep_all<<<16640 + 576, 256>>>(x, ws);

    cudaFuncSetAttribute(lorentz_mma_kernel,
                         cudaFuncAttributeMaxDynamicSharedMemorySize, SMEM_BYTES);
    lorentz_mma_kernel<<<1024, 256, SMEM_BYTES>>>(wti, out);
}